// round 15
// baseline (speedup 1.0000x reference)
#include <cuda_runtime.h>
#include <cuda_fp16.h>
#include <math.h>
#include <cstdint>

// ---------------------------------------------------------------------------
// Set2Set readout, 6 iterations of {attention readout, LSTM}.
// x converted to fp16 once; iter-0 readout = segment mean (in-pass).
// iter-0 GEMM runs K=256 (h=0 exact).
// GEMM: mma.sync.m16n8k16 fp16, CTA 128x64, 2-stage cp.async (single sync),
// 4 CTAs/SM, PERSISTENT over 2 M-tiles (grid = exactly one wave),
// LSTM epilogue staged through smem (coalesced global).
// ---------------------------------------------------------------------------

#define DIM 256
#define GDIM4 1024
#define KCAT 512
#define MAXG 8192
#define MAXN 200000

__device__ int    g_offs[MAXG + 1];
__device__ __half g_xh[(size_t)MAXN * DIM];
__device__ __half g_A0[MAXG * KCAT];          // [readout(256) | h(256)] fp16
__device__ __half g_A1[MAXG * KCAT];
__device__ __half g_Wcat[GDIM4 * KCAT];       // gate-interleaved rows: r = 4*d + q
__device__ float  g_bsum[GDIM4];
__device__ float  g_c[MAXG * DIM];
__device__ float  g_hraw[MAXG * DIM];

// ----------------------------- helpers ------------------------------------
__device__ __forceinline__ uint32_t smem_u32(const void* p) {
    uint32_t a;
    asm("{ .reg .u64 t; cvta.to.shared.u64 t, %1; cvt.u32.u64 %0, t; }"
        : "=r"(a) : "l"(p));
    return a;
}
__device__ __forceinline__ float sigm(float v) { return 1.f / (1.f + __expf(-v)); }
__device__ __forceinline__ float ftanh(float v) {
    float e = __expf(2.f * v);
    return 1.f - 2.f / (e + 1.f);
}

#define CP_ASYNC16(dst, src) \
    asm volatile("cp.async.cg.shared.global [%0], [%1], 16;" :: "r"(dst), "l"(src) : "memory")
#define CP_COMMIT() asm volatile("cp.async.commit_group;" ::: "memory")
#define LDMATRIX_X4(r0, r1, r2, r3, a) \
    asm volatile("ldmatrix.sync.aligned.m8n8.x4.shared.b16 {%0,%1,%2,%3}, [%4];" \
        : "=r"(r0), "=r"(r1), "=r"(r2), "=r"(r3) : "r"(a))

__device__ __forceinline__ void mma_f16(float* c, const uint32_t* a, const uint32_t* b) {
    asm volatile(
        "mma.sync.aligned.m16n8k16.row.col.f32.f16.f16.f32 "
        "{%0,%1,%2,%3}, {%4,%5,%6,%7}, {%8,%9}, {%0,%1,%2,%3};"
        : "+f"(c[0]), "+f"(c[1]), "+f"(c[2]), "+f"(c[3])
        : "r"(a[0]), "r"(a[1]), "r"(a[2]), "r"(a[3]), "r"(b[0]), "r"(b[1]));
}
__device__ __forceinline__ void unpack8(uint4 r, float* f) {
    __half2* hp = (__half2*)&r;
    float2 a = __half22float2(hp[0]); f[0] = a.x; f[1] = a.y;
    float2 b = __half22float2(hp[1]); f[2] = b.x; f[3] = b.y;
    float2 c = __half22float2(hp[2]); f[4] = c.x; f[5] = c.y;
    float2 d = __half22float2(hp[3]); f[6] = d.x; f[7] = d.y;
}

// --------------------------- setup (prep_w + zero_state) -------------------
__global__ void setup_kernel(const float* __restrict__ W_ih,
                             const float* __restrict__ W_hh,
                             const float* __restrict__ b_ih,
                             const float* __restrict__ b_hh, int G) {
    int idx = blockIdx.x * blockDim.x + threadIdx.x;
    if (idx < GDIM4 * KCAT) {
        int r = idx / KCAT, k = idx % KCAT;
        int d = r >> 2, q = r & 3;
        int n = q * DIM + d;
        float w = (k < DIM) ? W_ih[n * DIM + k] : W_hh[n * DIM + (k - DIM)];
        g_Wcat[idx] = __float2half_rn(w);
        if (k == 0) g_bsum[r] = b_ih[n] + b_hh[n];
    }
    if (idx < G * DIM) {
        g_c[idx] = 0.f;
        g_hraw[idx] = 0.f;
    }
}

__global__ void offsets_kernel(const int* __restrict__ batch, int N, int G) {
    int i = blockIdx.x * blockDim.x + threadIdx.x;
    if (i >= N) return;
    int cur = batch[i];
    if (i == 0) { for (int g = 0; g <= cur; ++g) g_offs[g] = 0; }
    else { int prev = batch[i - 1]; for (int g = prev + 1; g <= cur; ++g) g_offs[g] = i; }
    if (i == N - 1) { for (int g = cur + 1; g <= G; ++g) g_offs[g] = N; }
}

// ------------- convert x -> fp16 AND readout0 = segment mean ---------------
__global__ void __launch_bounds__(128)
convert_mean_kernel(const float* __restrict__ x, __half* __restrict__ buf, int G) {
    int g = blockIdx.x;
    int lane = threadIdx.x & 31, wid = threadIdx.x >> 5;
    int vs = g_offs[g], ve = g_offs[g + 1];

    __shared__ float sacc[4][256];

    float acc[8];
#pragma unroll
    for (int j = 0; j < 8; ++j) acc[j] = 0.f;

    for (int v = vs + wid; v < ve; v += 4) {
        const float4* xr = (const float4*)(x + (size_t)v * DIM);
        float4 X0 = __ldcs(xr + 2 * lane), X1 = __ldcs(xr + 2 * lane + 1);
        acc[0] += X0.x; acc[1] += X0.y; acc[2] += X0.z; acc[3] += X0.w;
        acc[4] += X1.x; acc[5] += X1.y; acc[6] += X1.z; acc[7] += X1.w;
        __half2 p0 = __floats2half2_rn(X0.x, X0.y);
        __half2 p1 = __floats2half2_rn(X0.z, X0.w);
        __half2 p2 = __floats2half2_rn(X1.x, X1.y);
        __half2 p3 = __floats2half2_rn(X1.z, X1.w);
        uint4 st;
        st.x = *(uint32_t*)&p0; st.y = *(uint32_t*)&p1;
        st.z = *(uint32_t*)&p2; st.w = *(uint32_t*)&p3;
        ((uint4*)(g_xh + (size_t)v * DIM))[lane] = st;
    }

    ((float4*)sacc[wid])[2 * lane]     = make_float4(acc[0], acc[1], acc[2], acc[3]);
    ((float4*)sacc[wid])[2 * lane + 1] = make_float4(acc[4], acc[5], acc[6], acc[7]);
    __syncthreads();

    float inv = 1.f / ((float)(ve - vs) + 1e-8f);
    int t = threadIdx.x;
    float2 p0 = ((const float2*)sacc[0])[t], p1 = ((const float2*)sacc[1])[t];
    float2 p2 = ((const float2*)sacc[2])[t], p3 = ((const float2*)sacc[3])[t];
    float r0 = (p0.x + p1.x + p2.x + p3.x) * inv;
    float r1 = (p0.y + p1.y + p2.y + p3.y) * inv;
    ((__half2*)buf)[(size_t)g * 256 + t] = __floats2half2_rn(r0, r1);
}

// --------------------- fused attention + readout (fp16 x) ------------------
__global__ void __launch_bounds__(128)
attn_kernel(__half* __restrict__ buf, float* __restrict__ out, int G, int last) {
    int g = blockIdx.x;
    int lane = threadIdx.x & 31, wid = threadIdx.x >> 5;
    int vs = g_offs[g], ve = g_offs[g + 1];

    __shared__ float sm[4], sd[4];
    __shared__ float sacc[4][256];

    const float4* hb = (const float4*)(g_hraw + (size_t)g * DIM);
    float4 hA = hb[2 * lane], hB = hb[2 * lane + 1];
    float h[8] = {hA.x, hA.y, hA.z, hA.w, hB.x, hB.y, hB.z, hB.w};
    float acc[8];
#pragma unroll
    for (int j = 0; j < 8; ++j) acc[j] = 0.f;
    float m = 0.f, dd = 0.f;

    const uint4* xb = (const uint4*)g_xh;
    int v = vs + wid;
    for (; v + 4 < ve; v += 8) {
        uint4 rA = __ldcs(xb + (size_t)v * 32 + lane);    // evict-first
        uint4 rB = __ldcs(xb + (size_t)(v + 4) * 32 + lane);
        float XA[8], XB[8];
        unpack8(rA, XA); unpack8(rB, XB);
        float pA = XA[0] * h[0], pB = XB[0] * h[0];
#pragma unroll
        for (int j = 1; j < 8; ++j) {
            pA = fmaf(XA[j], h[j], pA);
            pB = fmaf(XB[j], h[j], pB);
        }
#pragma unroll
        for (int o = 16; o; o >>= 1) {
            pA += __shfl_xor_sync(0xffffffffu, pA, o);
            pB += __shfl_xor_sync(0xffffffffu, pB, o);
        }
        float mn = fmaxf(m, fmaxf(pA, pB));
        float sc = __expf(m - mn), eA = __expf(pA - mn), eB = __expf(pB - mn);
        dd = dd * sc + eA + eB;
#pragma unroll
        for (int j = 0; j < 8; ++j)
            acc[j] = fmaf(acc[j], sc, fmaf(XA[j], eA, XB[j] * eB));
        m = mn;
    }
    if (v < ve) {
        uint4 rA = __ldcs(xb + (size_t)v * 32 + lane);
        float XA[8];
        unpack8(rA, XA);
        float p = XA[0] * h[0];
#pragma unroll
        for (int j = 1; j < 8; ++j) p = fmaf(XA[j], h[j], p);
#pragma unroll
        for (int o = 16; o; o >>= 1) p += __shfl_xor_sync(0xffffffffu, p, o);
        float mn = fmaxf(m, p);
        float sc = __expf(m - mn), e = __expf(p - mn);
        dd = dd * sc + e;
#pragma unroll
        for (int j = 0; j < 8; ++j) acc[j] = fmaf(acc[j], sc, XA[j] * e);
        m = mn;
    }

    if (lane == 0) { sm[wid] = m; sd[wid] = dd; }
    ((float4*)sacc[wid])[2 * lane]     = make_float4(acc[0], acc[1], acc[2], acc[3]);
    ((float4*)sacc[wid])[2 * lane + 1] = make_float4(acc[4], acc[5], acc[6], acc[7]);
    __syncthreads();

    float M = fmaxf(fmaxf(sm[0], sm[1]), fmaxf(sm[2], sm[3]));
    float e0 = __expf(sm[0] - M), e1 = __expf(sm[1] - M);
    float e2 = __expf(sm[2] - M), e3 = __expf(sm[3] - M);
    float D = sd[0] * e0 + sd[1] * e1 + sd[2] * e2 + sd[3] * e3;
    float inv = 1.f / (D + 1e-8f);

    int t = threadIdx.x;
    float2 p0 = ((const float2*)sacc[0])[t], p1 = ((const float2*)sacc[1])[t];
    float2 p2 = ((const float2*)sacc[2])[t], p3 = ((const float2*)sacc[3])[t];
    float r0 = (p0.x * e0 + p1.x * e1 + p2.x * e2 + p3.x * e3) * inv;
    float r1 = (p0.y * e0 + p1.y * e1 + p2.y * e2 + p3.y * e3) * inv;
    ((__half2*)buf)[(size_t)g * 256 + t] = __floats2half2_rn(r0, r1);
    if (last) {
        float2* o2 = (float2*)(out + (size_t)g * 512 + DIM);
        o2[t] = make_float2(r0, r1);
    }
}

// ------------------- fp16 mma.sync GEMM + fused LSTM -----------------------
// CTA tile 128(M)x64(N), 8 warps (4x2), warp tile 32x32, BK=64.
// 2 stages x 24KB smem, regs<=64 -> 4 CTAs/SM. Grid (16,32) = one wave;
// each CTA processes m-tiles by and by+32 (persistent, perfectly balanced).
#define NSTAGE 2
#define A_TILE 16384                   // 128 rows x 128B
#define B_TILE 8192                    // 64 rows x 128B
#define STAGE_BYTES (A_TILE + B_TILE)  // 24576
#define GEMM_SMEM (NSTAGE * STAGE_BYTES)
#define GS_STRIDE 66                   // staging row stride in floats (8B-aligned)
#define MTILE_STEP 32                  // grid.y

__global__ void __launch_bounds__(256, 4)
gemm_lstm_kernel(const __half* __restrict__ A, __half* __restrict__ Anext,
                 float* __restrict__ out, int M, int last, int nchunk) {
    extern __shared__ __align__(128) char smem[];
    uint32_t sbase = smem_u32(smem);
    const int tid = threadIdx.x;
    const int wid = tid >> 5, lane = tid & 31;
    const int wm = wid & 3, wn = wid >> 2;       // 4(M) x 2(N) warp grid
    const int bn = blockIdx.x;
    const int ntiles = (M + 127) >> 7;

    const int mgrp = lane >> 3, mrow = lane & 7;
    const int arow_off = ((mgrp & 1) << 3) + mrow;
    const int akb_off = mgrp >> 1;
    const int brow_off = ((mgrp >> 1) << 3) + mrow;
    const int bkb_off = mgrp & 1;

    uint32_t aRowBase[2], aSwz[2];
#pragma unroll
    for (int mt = 0; mt < 2; ++mt) {
        int row = wm * 32 + mt * 16 + arow_off;
        aRowBase[mt] = (uint32_t)row * 128;
        aSwz[mt] = (uint32_t)(row & 7);
    }
    uint32_t bRowBase[2], bSwz[2];
#pragma unroll
    for (int p = 0; p < 2; ++p) {
        int n = wn * 32 + p * 16 + brow_off;
        bRowBase[p] = (uint32_t)n * 128;
        bSwz[p] = (uint32_t)(n & 7);
    }

    for (int bm = blockIdx.y; bm < ntiles; bm += MTILE_STEP) {

        auto load_chunk = [&](int c, int s) {
#pragma unroll
            for (int i = 0; i < 6; ++i) {
                int q = i * 256 + tid;                // 0..1535
                uint32_t dst;
                const __half* src;
                if (q < 1024) {                       // A: 128 rows x 8 c4
                    int row = q >> 3, c4 = q & 7;
                    dst = sbase + s * STAGE_BYTES + (uint32_t)row * 128
                        + (uint32_t)((c4 ^ (row & 7)) << 4);
                    int rA = bm * 128 + row; if (rA >= M) rA = M - 1;
                    src = A + (size_t)rA * KCAT + c * 64 + c4 * 8;
                } else {                              // B: 64 rows x 8 c4
                    int qb = q - 1024;
                    int row = qb >> 3, c4 = qb & 7;
                    dst = sbase + s * STAGE_BYTES + A_TILE + (uint32_t)row * 128
                        + (uint32_t)((c4 ^ (row & 7)) << 4);
                    src = g_Wcat + (size_t)(bn * 64 + row) * KCAT + c * 64 + c4 * 8;
                }
                CP_ASYNC16(dst, src);
            }
            CP_COMMIT();
        };

        load_chunk(0, 0);    // prologue for this tile

        float acc[2][4][4];
#pragma unroll
        for (int mt = 0; mt < 2; ++mt)
#pragma unroll
            for (int nt = 0; nt < 4; ++nt)
#pragma unroll
                for (int r = 0; r < 4; ++r) acc[mt][nt][r] = 0.f;

        // single-sync double-buffered mainloop
        for (int c = 0; c < nchunk; ++c) {
            const int s = c & 1;
            asm volatile("cp.async.wait_group 0;" ::: "memory");
            __syncthreads();   // publish chunk c; all warps done with c-1
            if (c + 1 < nchunk) load_chunk(c + 1, (c + 1) & 1);
            uint32_t aS = sbase + (uint32_t)s * STAGE_BYTES;
            uint32_t bS = aS + A_TILE;
#pragma unroll
            for (int kk = 0; kk < 4; ++kk) {
                uint32_t af[2][4], bf[4][2];
#pragma unroll
                for (int mt = 0; mt < 2; ++mt) {
                    uint32_t kb = (uint32_t)(kk * 2 + akb_off) ^ aSwz[mt];
                    LDMATRIX_X4(af[mt][0], af[mt][1], af[mt][2], af[mt][3],
                                aS + aRowBase[mt] + (kb << 4));
                }
#pragma unroll
                for (int p = 0; p < 2; ++p) {
                    uint32_t kb = (uint32_t)(kk * 2 + bkb_off) ^ bSwz[p];
                    LDMATRIX_X4(bf[2 * p][0], bf[2 * p][1], bf[2 * p + 1][0], bf[2 * p + 1][1],
                                bS + bRowBase[p] + (kb << 4));
                }
#pragma unroll
                for (int mt = 0; mt < 2; ++mt)
#pragma unroll
                    for (int nt = 0; nt < 4; ++nt)
                        mma_f16(acc[mt][nt], af[mt], bf[nt]);
            }
        }
        __syncthreads();   // last chunk's smem reads done before staging reuse

        // ---- epilogue phase 1: stage raw gate fragments to smem ----
        float* gs = (float*)smem;              // [128][GS_STRIDE]
        {
            const int grow = wm * 32 + (lane >> 2);
            const int gcol = wn * 32 + (lane & 3) * 2;
#pragma unroll
            for (int mt = 0; mt < 2; ++mt)
#pragma unroll
                for (int nt = 0; nt < 4; ++nt) {
                    int r0 = grow + mt * 16;
                    int cc = gcol + nt * 8;
                    *(float2*)&gs[r0 * GS_STRIDE + cc] =
                        make_float2(acc[mt][nt][0], acc[mt][nt][1]);
                    *(float2*)&gs[(r0 + 8) * GS_STRIDE + cc] =
                        make_float2(acc[mt][nt][2], acc[mt][nt][3]);
                }
        }
        __syncthreads();

        // ---- epilogue phase 2: coalesced LSTM (thread = half g-row) ----
        {
            int gl = tid >> 1, half = tid & 1;
            int g = bm * 128 + gl;
            if (g < M) {
                const float* row = gs + gl * GS_STRIDE + half * 32;
                const float4* bs = (const float4*)(g_bsum + bn * 64 + half * 32);
                int dg = bn * 16 + half * 8;
                float* crow = g_c + (size_t)g * DIM + dg;
                float cv[8], hv[8];
#pragma unroll
                for (int i = 0; i < 8; ++i) {
                    float2 v01 = *(const float2*)(row + i * 4);
                    float2 v23 = *(const float2*)(row + i * 4 + 2);
                    float4 b = __ldg(bs + i);
                    float gi = sigm(v01.x + b.x);
                    float gf = sigm(v01.y + b.y);
                    float gg = ftanh(v23.x + b.z);
                    float go = sigm(v23.y + b.w);
                    float cn = gf * crow[i] + gi * gg;
                    cv[i] = cn;
                    hv[i] = go * ftanh(cn);
                }
                if (last) {
                    float4* o = (float4*)(out + (size_t)g * 512 + dg);
                    o[0] = make_float4(hv[0], hv[1], hv[2], hv[3]);
                    o[1] = make_float4(hv[4], hv[5], hv[6], hv[7]);
                } else {
                    float4* cw = (float4*)crow;
                    cw[0] = make_float4(cv[0], cv[1], cv[2], cv[3]);
                    cw[1] = make_float4(cv[4], cv[5], cv[6], cv[7]);
                    __half2 hh[4];
                    float hr[8];
#pragma unroll
                    for (int i = 0; i < 4; ++i) {
                        hh[i] = __floats2half2_rn(hv[2 * i], hv[2 * i + 1]);
                        float2 back = __half22float2(hh[i]);
                        hr[2 * i] = back.x; hr[2 * i + 1] = back.y;
                    }
                    *(uint4*)(Anext + (size_t)g * KCAT + DIM + dg) = *(uint4*)hh;
                    float4* hw = (float4*)(g_hraw + (size_t)g * DIM + dg);
                    hw[0] = make_float4(hr[0], hr[1], hr[2], hr[3]);
                    hw[1] = make_float4(hr[4], hr[5], hr[6], hr[7]);
                }
            }
        }
        __syncthreads();   // phase-2 smem reads done before next tile's prologue
    }
}

// ------------------------------ launch -------------------------------------
extern "C" void kernel_launch(void* const* d_in, const int* in_sizes, int n_in,
                              void* d_out, int out_size) {
    const float* x     = (const float*)d_in[0];
    const int*   batch = (const int*)d_in[1];
    const float* W_ih  = (const float*)d_in[3];
    const float* W_hh  = (const float*)d_in[4];
    const float* b_ih  = (const float*)d_in[5];
    const float* b_hh  = (const float*)d_in[6];
    float* out = (float*)d_out;

    int N = in_sizes[1];
    int G = out_size / (2 * DIM);

    __half *A0, *A1;
    cudaGetSymbolAddress((void**)&A0, g_A0);
    cudaGetSymbolAddress((void**)&A1, g_A1);

    cudaFuncSetAttribute(gemm_lstm_kernel,
                         cudaFuncAttributeMaxDynamicSharedMemorySize, GEMM_SMEM);

    // launch order: index 3 = gemm0 (ncu profile slot)
    setup_kernel<<<(G * DIM + 255) / 256, 256>>>(W_ih, W_hh, b_ih, b_hh, G); // 0
    offsets_kernel<<<(N + 255) / 256, 256>>>(batch, N, G);                   // 1
    convert_mean_kernel<<<G, 128>>>(x, A0, G);                               // 2

    dim3 gemm_grid(GDIM4 / 64, MTILE_STEP);   // (16, 32) = one full wave
    for (int it = 0; it < 6; ++it) {
        __half* cur = (it & 1) ? A1 : A0;
        __half* nxt = (it & 1) ? A0 : A1;
        int last = (it == 5) ? 1 : 0;
        int nchunk = (it == 0) ? 4 : 8;   // iter0: h==0, K=256 exact
        if (it > 0) attn_kernel<<<G, 128>>>(cur, out, G, last);
        gemm_lstm_kernel<<<gemm_grid, 256, GEMM_SMEM>>>(cur, nxt, out, G, last, nchunk);
    }
}

// round 16
// speedup vs baseline: 1.0154x; 1.0154x over previous
#include <cuda_runtime.h>
#include <cuda_fp16.h>
#include <math.h>
#include <cstdint>

// ---------------------------------------------------------------------------
// Set2Set readout, 6 iterations of {attention readout, LSTM}.
// x converted to fp16 once; iter-0 readout = segment mean (in-pass).
// iter-0 GEMM runs K=256 (h=0 exact).
// GEMM: mma.sync.m16n8k16 fp16, CTA 128x64, 2-stage cp.async (single sync),
// 4 CTAs/SM, non-persistent grid (R14 optimum), staged LSTM epilogue.
// attn: 2 graphs per 256-thread block (4 warps each), online softmax merge.
// ---------------------------------------------------------------------------

#define DIM 256
#define GDIM4 1024
#define KCAT 512
#define MAXG 8192
#define MAXN 200000

__device__ int    g_offs[MAXG + 1];
__device__ __half g_xh[(size_t)MAXN * DIM];
__device__ __half g_A0[MAXG * KCAT];          // [readout(256) | h(256)] fp16
__device__ __half g_A1[MAXG * KCAT];
__device__ __half g_Wcat[GDIM4 * KCAT];       // gate-interleaved rows: r = 4*d + q
__device__ float  g_bsum[GDIM4];
__device__ float  g_c[MAXG * DIM];
__device__ float  g_hraw[MAXG * DIM];

// ----------------------------- helpers ------------------------------------
__device__ __forceinline__ uint32_t smem_u32(const void* p) {
    uint32_t a;
    asm("{ .reg .u64 t; cvta.to.shared.u64 t, %1; cvt.u32.u64 %0, t; }"
        : "=r"(a) : "l"(p));
    return a;
}
__device__ __forceinline__ float sigm(float v) { return 1.f / (1.f + __expf(-v)); }
__device__ __forceinline__ float ftanh(float v) {
    float e = __expf(2.f * v);
    return 1.f - 2.f / (e + 1.f);
}

#define CP_ASYNC16(dst, src) \
    asm volatile("cp.async.cg.shared.global [%0], [%1], 16;" :: "r"(dst), "l"(src) : "memory")
#define CP_COMMIT() asm volatile("cp.async.commit_group;" ::: "memory")
#define LDMATRIX_X4(r0, r1, r2, r3, a) \
    asm volatile("ldmatrix.sync.aligned.m8n8.x4.shared.b16 {%0,%1,%2,%3}, [%4];" \
        : "=r"(r0), "=r"(r1), "=r"(r2), "=r"(r3) : "r"(a))

__device__ __forceinline__ void mma_f16(float* c, const uint32_t* a, const uint32_t* b) {
    asm volatile(
        "mma.sync.aligned.m16n8k16.row.col.f32.f16.f16.f32 "
        "{%0,%1,%2,%3}, {%4,%5,%6,%7}, {%8,%9}, {%0,%1,%2,%3};"
        : "+f"(c[0]), "+f"(c[1]), "+f"(c[2]), "+f"(c[3])
        : "r"(a[0]), "r"(a[1]), "r"(a[2]), "r"(a[3]), "r"(b[0]), "r"(b[1]));
}
__device__ __forceinline__ void unpack8(uint4 r, float* f) {
    __half2* hp = (__half2*)&r;
    float2 a = __half22float2(hp[0]); f[0] = a.x; f[1] = a.y;
    float2 b = __half22float2(hp[1]); f[2] = b.x; f[3] = b.y;
    float2 c = __half22float2(hp[2]); f[4] = c.x; f[5] = c.y;
    float2 d = __half22float2(hp[3]); f[6] = d.x; f[7] = d.y;
}

// --------------------------- setup (prep_w + zero_state) -------------------
__global__ void setup_kernel(const float* __restrict__ W_ih,
                             const float* __restrict__ W_hh,
                             const float* __restrict__ b_ih,
                             const float* __restrict__ b_hh, int G) {
    int idx = blockIdx.x * blockDim.x + threadIdx.x;
    if (idx < GDIM4 * KCAT) {
        int r = idx / KCAT, k = idx % KCAT;
        int d = r >> 2, q = r & 3;
        int n = q * DIM + d;
        float w = (k < DIM) ? W_ih[n * DIM + k] : W_hh[n * DIM + (k - DIM)];
        g_Wcat[idx] = __float2half_rn(w);
        if (k == 0) g_bsum[r] = b_ih[n] + b_hh[n];
    }
    if (idx < G * DIM) {
        g_c[idx] = 0.f;
        g_hraw[idx] = 0.f;
    }
}

__global__ void offsets_kernel(const int* __restrict__ batch, int N, int G) {
    int i = blockIdx.x * blockDim.x + threadIdx.x;
    if (i >= N) return;
    int cur = batch[i];
    if (i == 0) { for (int g = 0; g <= cur; ++g) g_offs[g] = 0; }
    else { int prev = batch[i - 1]; for (int g = prev + 1; g <= cur; ++g) g_offs[g] = i; }
    if (i == N - 1) { for (int g = cur + 1; g <= G; ++g) g_offs[g] = N; }
}

// ------------- convert x -> fp16 AND readout0 = segment mean ---------------
__global__ void __launch_bounds__(128)
convert_mean_kernel(const float* __restrict__ x, __half* __restrict__ buf, int G) {
    int g = blockIdx.x;
    int lane = threadIdx.x & 31, wid = threadIdx.x >> 5;
    int vs = g_offs[g], ve = g_offs[g + 1];

    __shared__ float sacc[4][256];

    float acc[8];
#pragma unroll
    for (int j = 0; j < 8; ++j) acc[j] = 0.f;

    for (int v = vs + wid; v < ve; v += 4) {
        const float4* xr = (const float4*)(x + (size_t)v * DIM);
        float4 X0 = __ldcs(xr + 2 * lane), X1 = __ldcs(xr + 2 * lane + 1);
        acc[0] += X0.x; acc[1] += X0.y; acc[2] += X0.z; acc[3] += X0.w;
        acc[4] += X1.x; acc[5] += X1.y; acc[6] += X1.z; acc[7] += X1.w;
        __half2 p0 = __floats2half2_rn(X0.x, X0.y);
        __half2 p1 = __floats2half2_rn(X0.z, X0.w);
        __half2 p2 = __floats2half2_rn(X1.x, X1.y);
        __half2 p3 = __floats2half2_rn(X1.z, X1.w);
        uint4 st;
        st.x = *(uint32_t*)&p0; st.y = *(uint32_t*)&p1;
        st.z = *(uint32_t*)&p2; st.w = *(uint32_t*)&p3;
        ((uint4*)(g_xh + (size_t)v * DIM))[lane] = st;
    }

    ((float4*)sacc[wid])[2 * lane]     = make_float4(acc[0], acc[1], acc[2], acc[3]);
    ((float4*)sacc[wid])[2 * lane + 1] = make_float4(acc[4], acc[5], acc[6], acc[7]);
    __syncthreads();

    float inv = 1.f / ((float)(ve - vs) + 1e-8f);
    int t = threadIdx.x;
    float2 p0 = ((const float2*)sacc[0])[t], p1 = ((const float2*)sacc[1])[t];
    float2 p2 = ((const float2*)sacc[2])[t], p3 = ((const float2*)sacc[3])[t];
    float r0 = (p0.x + p1.x + p2.x + p3.x) * inv;
    float r1 = (p0.y + p1.y + p2.y + p3.y) * inv;
    ((__half2*)buf)[(size_t)g * 256 + t] = __floats2half2_rn(r0, r1);
}

// --------------------- fused attention + readout (fp16 x) ------------------
// 256 threads = 2 graphs per block; warps 0-3 -> graph 2b, warps 4-7 -> 2b+1.
__global__ void __launch_bounds__(256)
attn_kernel(__half* __restrict__ buf, float* __restrict__ out, int G, int last) {
    int tid = threadIdx.x;
    int lane = tid & 31, w = tid >> 5;
    int sub = w & 3;              // warp index within graph group
    int gslot = w >> 2;           // 0 or 1
    int g = blockIdx.x * 2 + gslot;

    __shared__ float sm[2][4], sd[2][4];
    __shared__ float sacc[2][4][256];

    if (g < G) {
        int vs = g_offs[g], ve = g_offs[g + 1];

        const float4* hb = (const float4*)(g_hraw + (size_t)g * DIM);
        float4 hA = hb[2 * lane], hB = hb[2 * lane + 1];
        float h[8] = {hA.x, hA.y, hA.z, hA.w, hB.x, hB.y, hB.z, hB.w};
        float acc[8];
#pragma unroll
        for (int j = 0; j < 8; ++j) acc[j] = 0.f;
        float m = 0.f, dd = 0.f;

        const uint4* xb = (const uint4*)g_xh;
        int v = vs + sub;
        for (; v + 4 < ve; v += 8) {
            uint4 rA = __ldcs(xb + (size_t)v * 32 + lane);    // evict-first
            uint4 rB = __ldcs(xb + (size_t)(v + 4) * 32 + lane);
            float XA[8], XB[8];
            unpack8(rA, XA); unpack8(rB, XB);
            float pA = XA[0] * h[0], pB = XB[0] * h[0];
#pragma unroll
            for (int j = 1; j < 8; ++j) {
                pA = fmaf(XA[j], h[j], pA);
                pB = fmaf(XB[j], h[j], pB);
            }
#pragma unroll
            for (int o = 16; o; o >>= 1) {
                pA += __shfl_xor_sync(0xffffffffu, pA, o);
                pB += __shfl_xor_sync(0xffffffffu, pB, o);
            }
            float mn = fmaxf(m, fmaxf(pA, pB));
            float sc = __expf(m - mn), eA = __expf(pA - mn), eB = __expf(pB - mn);
            dd = dd * sc + eA + eB;
#pragma unroll
            for (int j = 0; j < 8; ++j)
                acc[j] = fmaf(acc[j], sc, fmaf(XA[j], eA, XB[j] * eB));
            m = mn;
        }
        if (v < ve) {
            uint4 rA = __ldcs(xb + (size_t)v * 32 + lane);
            float XA[8];
            unpack8(rA, XA);
            float p = XA[0] * h[0];
#pragma unroll
            for (int j = 1; j < 8; ++j) p = fmaf(XA[j], h[j], p);
#pragma unroll
            for (int o = 16; o; o >>= 1) p += __shfl_xor_sync(0xffffffffu, p, o);
            float mn = fmaxf(m, p);
            float sc = __expf(m - mn), e = __expf(p - mn);
            dd = dd * sc + e;
#pragma unroll
            for (int j = 0; j < 8; ++j) acc[j] = fmaf(acc[j], sc, XA[j] * e);
            m = mn;
        }

        if (lane == 0) { sm[gslot][sub] = m; sd[gslot][sub] = dd; }
        ((float4*)sacc[gslot][sub])[2 * lane]     = make_float4(acc[0], acc[1], acc[2], acc[3]);
        ((float4*)sacc[gslot][sub])[2 * lane + 1] = make_float4(acc[4], acc[5], acc[6], acc[7]);
    }
    __syncthreads();

    // merge: threads 0-127 -> graph 2b, 128-255 -> graph 2b+1; each does 2 dims
    int gs2 = tid >> 7;
    int tt = tid & 127;
    int g2 = blockIdx.x * 2 + gs2;
    if (g2 < G) {
        float M = fmaxf(fmaxf(sm[gs2][0], sm[gs2][1]), fmaxf(sm[gs2][2], sm[gs2][3]));
        float e0 = __expf(sm[gs2][0] - M), e1 = __expf(sm[gs2][1] - M);
        float e2 = __expf(sm[gs2][2] - M), e3 = __expf(sm[gs2][3] - M);
        float D = sd[gs2][0] * e0 + sd[gs2][1] * e1 + sd[gs2][2] * e2 + sd[gs2][3] * e3;
        float inv = 1.f / (D + 1e-8f);

        float2 p0 = ((const float2*)sacc[gs2][0])[tt], p1 = ((const float2*)sacc[gs2][1])[tt];
        float2 p2 = ((const float2*)sacc[gs2][2])[tt], p3 = ((const float2*)sacc[gs2][3])[tt];
        float r0 = (p0.x * e0 + p1.x * e1 + p2.x * e2 + p3.x * e3) * inv;
        float r1 = (p0.y * e0 + p1.y * e1 + p2.y * e2 + p3.y * e3) * inv;
        ((__half2*)buf)[(size_t)g2 * 256 + tt] = __floats2half2_rn(r0, r1);
        if (last) {
            float2* o2 = (float2*)(out + (size_t)g2 * 512 + DIM);
            o2[tt] = make_float2(r0, r1);
        }
    }
}

// ------------------- fp16 mma.sync GEMM + fused LSTM (R14) -----------------
// CTA tile 128(M)x64(N), 8 warps (4x2), warp tile 32x32, BK=64.
// 2 stages x 24KB smem, regs<=64 -> 4 CTAs/SM.
// Single __syncthreads per chunk: wait(0) -> sync -> load(c+1) -> compute(c).
#define NSTAGE 2
#define A_TILE 16384                   // 128 rows x 128B
#define B_TILE 8192                    // 64 rows x 128B
#define STAGE_BYTES (A_TILE + B_TILE)  // 24576
#define GEMM_SMEM (NSTAGE * STAGE_BYTES)
#define GS_STRIDE 66                   // staging row stride in floats (8B-aligned)

__global__ void __launch_bounds__(256, 4)
gemm_lstm_kernel(const __half* __restrict__ A, __half* __restrict__ Anext,
                 float* __restrict__ out, int M, int last, int nchunk) {
    extern __shared__ __align__(128) char smem[];
    uint32_t sbase = smem_u32(smem);
    const int tid = threadIdx.x;
    const int wid = tid >> 5, lane = tid & 31;
    const int wm = wid & 3, wn = wid >> 2;       // 4(M) x 2(N) warp grid
    const int bn = blockIdx.x, bm = blockIdx.y;

    auto load_chunk = [&](int c, int s) {
#pragma unroll
        for (int i = 0; i < 6; ++i) {
            int q = i * 256 + tid;                // 0..1535
            uint32_t dst;
            const __half* src;
            if (q < 1024) {                       // A: 128 rows x 8 c4
                int row = q >> 3, c4 = q & 7;
                dst = sbase + s * STAGE_BYTES + (uint32_t)row * 128
                    + (uint32_t)((c4 ^ (row & 7)) << 4);
                int rA = bm * 128 + row; if (rA >= M) rA = M - 1;
                src = A + (size_t)rA * KCAT + c * 64 + c4 * 8;
            } else {                              // B: 64 rows x 8 c4
                int qb = q - 1024;
                int row = qb >> 3, c4 = qb & 7;
                dst = sbase + s * STAGE_BYTES + A_TILE + (uint32_t)row * 128
                    + (uint32_t)((c4 ^ (row & 7)) << 4);
                src = g_Wcat + (size_t)(bn * 64 + row) * KCAT + c * 64 + c4 * 8;
            }
            CP_ASYNC16(dst, src);
        }
        CP_COMMIT();
    };

    load_chunk(0, 0);    // prologue

    float acc[2][4][4];
#pragma unroll
    for (int mt = 0; mt < 2; ++mt)
#pragma unroll
        for (int nt = 0; nt < 4; ++nt)
#pragma unroll
            for (int r = 0; r < 4; ++r) acc[mt][nt][r] = 0.f;

    const int mgrp = lane >> 3, mrow = lane & 7;
    const int arow_off = ((mgrp & 1) << 3) + mrow;
    const int akb_off = mgrp >> 1;
    const int brow_off = ((mgrp >> 1) << 3) + mrow;
    const int bkb_off = mgrp & 1;

    uint32_t aRowBase[2], aSwz[2];
#pragma unroll
    for (int mt = 0; mt < 2; ++mt) {
        int row = wm * 32 + mt * 16 + arow_off;
        aRowBase[mt] = (uint32_t)row * 128;
        aSwz[mt] = (uint32_t)(row & 7);
    }
    uint32_t bRowBase[2], bSwz[2];
#pragma unroll
    for (int p = 0; p < 2; ++p) {
        int n = wn * 32 + p * 16 + brow_off;
        bRowBase[p] = (uint32_t)n * 128;
        bSwz[p] = (uint32_t)(n & 7);
    }

    // single-sync double-buffered mainloop
    for (int c = 0; c < nchunk; ++c) {
        const int s = c & 1;
        asm volatile("cp.async.wait_group 0;" ::: "memory");   // chunk c landed
        __syncthreads();   // publish chunk c; all warps done computing c-1
        if (c + 1 < nchunk) load_chunk(c + 1, (c + 1) & 1);    // stage free (WAR ok)
        uint32_t aS = sbase + (uint32_t)s * STAGE_BYTES;
        uint32_t bS = aS + A_TILE;
#pragma unroll
        for (int kk = 0; kk < 4; ++kk) {
            uint32_t af[2][4], bf[4][2];
#pragma unroll
            for (int mt = 0; mt < 2; ++mt) {
                uint32_t kb = (uint32_t)(kk * 2 + akb_off) ^ aSwz[mt];
                LDMATRIX_X4(af[mt][0], af[mt][1], af[mt][2], af[mt][3],
                            aS + aRowBase[mt] + (kb << 4));
            }
#pragma unroll
            for (int p = 0; p < 2; ++p) {
                uint32_t kb = (uint32_t)(kk * 2 + bkb_off) ^ bSwz[p];
                LDMATRIX_X4(bf[2 * p][0], bf[2 * p][1], bf[2 * p + 1][0], bf[2 * p + 1][1],
                            bS + bRowBase[p] + (kb << 4));
            }
#pragma unroll
            for (int mt = 0; mt < 2; ++mt)
#pragma unroll
                for (int nt = 0; nt < 4; ++nt)
                    mma_f16(acc[mt][nt], af[mt], bf[nt]);
        }
    }
    __syncthreads();   // last chunk's smem reads done before staging reuses smem

    // ---- epilogue phase 1: stage raw gate fragments to smem ----
    float* gs = (float*)smem;              // [128][GS_STRIDE]
    {
        const int grow = wm * 32 + (lane >> 2);
        const int gcol = wn * 32 + (lane & 3) * 2;
#pragma unroll
        for (int mt = 0; mt < 2; ++mt)
#pragma unroll
            for (int nt = 0; nt < 4; ++nt) {
                int r0 = grow + mt * 16;
                int cc = gcol + nt * 8;
                *(float2*)&gs[r0 * GS_STRIDE + cc] =
                    make_float2(acc[mt][nt][0], acc[mt][nt][1]);
                *(float2*)&gs[(r0 + 8) * GS_STRIDE + cc] =
                    make_float2(acc[mt][nt][2], acc[mt][nt][3]);
            }
    }
    __syncthreads();

    // ---- epilogue phase 2: coalesced LSTM (thread = half g-row, 8 d) ----
    {
        int gl = tid >> 1, half = tid & 1;
        int g = bm * 128 + gl;
        if (g < M) {
            const float* row = gs + gl * GS_STRIDE + half * 32;   // 8B-aligned
            const float4* bs = (const float4*)(g_bsum + bn * 64 + half * 32);
            int dg = bn * 16 + half * 8;
            float* crow = g_c + (size_t)g * DIM + dg;
            float cv[8], hv[8];
#pragma unroll
            for (int i = 0; i < 8; ++i) {
                float2 v01 = *(const float2*)(row + i * 4);
                float2 v23 = *(const float2*)(row + i * 4 + 2);
                float4 b = __ldg(bs + i);
                float gi = sigm(v01.x + b.x);
                float gf = sigm(v01.y + b.y);
                float gg = ftanh(v23.x + b.z);
                float go = sigm(v23.y + b.w);
                float cn = gf * crow[i] + gi * gg;
                cv[i] = cn;
                hv[i] = go * ftanh(cn);
            }
            if (last) {
                float4* o = (float4*)(out + (size_t)g * 512 + dg);
                o[0] = make_float4(hv[0], hv[1], hv[2], hv[3]);
                o[1] = make_float4(hv[4], hv[5], hv[6], hv[7]);
            } else {
                float4* cw = (float4*)crow;
                cw[0] = make_float4(cv[0], cv[1], cv[2], cv[3]);
                cw[1] = make_float4(cv[4], cv[5], cv[6], cv[7]);
                __half2 hh[4];
                float hr[8];
#pragma unroll
                for (int i = 0; i < 4; ++i) {
                    hh[i] = __floats2half2_rn(hv[2 * i], hv[2 * i + 1]);
                    float2 back = __half22float2(hh[i]);
                    hr[2 * i] = back.x; hr[2 * i + 1] = back.y;
                }
                *(uint4*)(Anext + (size_t)g * KCAT + DIM + dg) = *(uint4*)hh;
                float4* hw = (float4*)(g_hraw + (size_t)g * DIM + dg);
                hw[0] = make_float4(hr[0], hr[1], hr[2], hr[3]);
                hw[1] = make_float4(hr[4], hr[5], hr[6], hr[7]);
            }
        }
    }
}

// ------------------------------ launch -------------------------------------
extern "C" void kernel_launch(void* const* d_in, const int* in_sizes, int n_in,
                              void* d_out, int out_size) {
    const float* x     = (const float*)d_in[0];
    const int*   batch = (const int*)d_in[1];
    const float* W_ih  = (const float*)d_in[3];
    const float* W_hh  = (const float*)d_in[4];
    const float* b_ih  = (const float*)d_in[5];
    const float* b_hh  = (const float*)d_in[6];
    float* out = (float*)d_out;

    int N = in_sizes[1];
    int G = out_size / (2 * DIM);

    __half *A0, *A1;
    cudaGetSymbolAddress((void**)&A0, g_A0);
    cudaGetSymbolAddress((void**)&A1, g_A1);

    cudaFuncSetAttribute(gemm_lstm_kernel,
                         cudaFuncAttributeMaxDynamicSharedMemorySize, GEMM_SMEM);

    // launch order: index 3 = gemm0 (ncu profile slot)
    setup_kernel<<<(G * DIM + 255) / 256, 256>>>(W_ih, W_hh, b_ih, b_hh, G); // 0
    offsets_kernel<<<(N + 255) / 256, 256>>>(batch, N, G);                   // 1
    convert_mean_kernel<<<G, 128>>>(x, A0, G);                               // 2

    dim3 gemm_grid(GDIM4 / 64, (G + 127) / 128);    // non-persistent (R14)
    for (int it = 0; it < 6; ++it) {
        __half* cur = (it & 1) ? A1 : A0;
        __half* nxt = (it & 1) ? A0 : A1;
        int last = (it == 5) ? 1 : 0;
        int nchunk = (it == 0) ? 4 : 8;   // iter0: h==0, K=256 exact
        if (it > 0) attn_kernel<<<(G + 1) / 2, 256>>>(cur, out, G, last);
        gemm_lstm_kernel<<<gemm_grid, 256, GEMM_SMEM>>>(cur, nxt, out, G, last, nchunk);
    }
}

// round 17
// speedup vs baseline: 1.1221x; 1.1051x over previous
#include <cuda_runtime.h>
#include <cuda_fp16.h>
#include <math.h>
#include <cstdint>

// ---------------------------------------------------------------------------
// Set2Set readout, 6 iterations of {attention readout, LSTM}.
// x converted to fp16 once; iter-0 readout = segment mean (in-pass).
// iter-0 GEMM runs K=256 (h=0 exact).
// GEMM: mma.sync.m16n8k16 fp16, CTA 128x64, 2-stage cp.async (single sync),
// 4 CTAs/SM, non-persistent grid, staged LSTM epilogue (coalesced).
// attn: 1 graph per 128-thread block (R14 optimum); h read as fp16 from the
// A-buffer (bit-identical to the old g_hraw float path, one less array).
// ---------------------------------------------------------------------------

#define DIM 256
#define GDIM4 1024
#define KCAT 512
#define MAXG 8192
#define MAXN 200000

__device__ int    g_offs[MAXG + 1];
__device__ __half g_xh[(size_t)MAXN * DIM];
__device__ __half g_A0[MAXG * KCAT];          // [readout(256) | h(256)] fp16
__device__ __half g_A1[MAXG * KCAT];
__device__ __half g_Wcat[GDIM4 * KCAT];       // gate-interleaved rows: r = 4*d + q
__device__ float  g_bsum[GDIM4];
__device__ float  g_c[MAXG * DIM];

// ----------------------------- helpers ------------------------------------
__device__ __forceinline__ uint32_t smem_u32(const void* p) {
    uint32_t a;
    asm("{ .reg .u64 t; cvta.to.shared.u64 t, %1; cvt.u32.u64 %0, t; }"
        : "=r"(a) : "l"(p));
    return a;
}
__device__ __forceinline__ float sigm(float v) { return 1.f / (1.f + __expf(-v)); }
__device__ __forceinline__ float ftanh(float v) {
    float e = __expf(2.f * v);
    return 1.f - 2.f / (e + 1.f);
}

#define CP_ASYNC16(dst, src) \
    asm volatile("cp.async.cg.shared.global [%0], [%1], 16;" :: "r"(dst), "l"(src) : "memory")
#define CP_COMMIT() asm volatile("cp.async.commit_group;" ::: "memory")
#define LDMATRIX_X4(r0, r1, r2, r3, a) \
    asm volatile("ldmatrix.sync.aligned.m8n8.x4.shared.b16 {%0,%1,%2,%3}, [%4];" \
        : "=r"(r0), "=r"(r1), "=r"(r2), "=r"(r3) : "r"(a))

__device__ __forceinline__ void mma_f16(float* c, const uint32_t* a, const uint32_t* b) {
    asm volatile(
        "mma.sync.aligned.m16n8k16.row.col.f32.f16.f16.f32 "
        "{%0,%1,%2,%3}, {%4,%5,%6,%7}, {%8,%9}, {%0,%1,%2,%3};"
        : "+f"(c[0]), "+f"(c[1]), "+f"(c[2]), "+f"(c[3])
        : "r"(a[0]), "r"(a[1]), "r"(a[2]), "r"(a[3]), "r"(b[0]), "r"(b[1]));
}
__device__ __forceinline__ void unpack8(uint4 r, float* f) {
    __half2* hp = (__half2*)&r;
    float2 a = __half22float2(hp[0]); f[0] = a.x; f[1] = a.y;
    float2 b = __half22float2(hp[1]); f[2] = b.x; f[3] = b.y;
    float2 c = __half22float2(hp[2]); f[4] = c.x; f[5] = c.y;
    float2 d = __half22float2(hp[3]); f[6] = d.x; f[7] = d.y;
}

// --------------------------- setup (prep_w + zero_state) -------------------
__global__ void setup_kernel(const float* __restrict__ W_ih,
                             const float* __restrict__ W_hh,
                             const float* __restrict__ b_ih,
                             const float* __restrict__ b_hh, int G) {
    int idx = blockIdx.x * blockDim.x + threadIdx.x;
    if (idx < GDIM4 * KCAT) {
        int r = idx / KCAT, k = idx % KCAT;
        int d = r >> 2, q = r & 3;
        int n = q * DIM + d;
        float w = (k < DIM) ? W_ih[n * DIM + k] : W_hh[n * DIM + (k - DIM)];
        g_Wcat[idx] = __float2half_rn(w);
        if (k == 0) g_bsum[r] = b_ih[n] + b_hh[n];
    }
    if (idx < G * DIM) {
        g_c[idx] = 0.f;
    }
}

__global__ void offsets_kernel(const int* __restrict__ batch, int N, int G) {
    int i = blockIdx.x * blockDim.x + threadIdx.x;
    if (i >= N) return;
    int cur = batch[i];
    if (i == 0) { for (int g = 0; g <= cur; ++g) g_offs[g] = 0; }
    else { int prev = batch[i - 1]; for (int g = prev + 1; g <= cur; ++g) g_offs[g] = i; }
    if (i == N - 1) { for (int g = cur + 1; g <= G; ++g) g_offs[g] = N; }
}

// ------------- convert x -> fp16 AND readout0 = segment mean ---------------
__global__ void __launch_bounds__(128)
convert_mean_kernel(const float* __restrict__ x, __half* __restrict__ buf, int G) {
    int g = blockIdx.x;
    int lane = threadIdx.x & 31, wid = threadIdx.x >> 5;
    int vs = g_offs[g], ve = g_offs[g + 1];

    __shared__ float sacc[4][256];

    float acc[8];
#pragma unroll
    for (int j = 0; j < 8; ++j) acc[j] = 0.f;

    for (int v = vs + wid; v < ve; v += 4) {
        const float4* xr = (const float4*)(x + (size_t)v * DIM);
        float4 X0 = __ldcs(xr + 2 * lane), X1 = __ldcs(xr + 2 * lane + 1);
        acc[0] += X0.x; acc[1] += X0.y; acc[2] += X0.z; acc[3] += X0.w;
        acc[4] += X1.x; acc[5] += X1.y; acc[6] += X1.z; acc[7] += X1.w;
        __half2 p0 = __floats2half2_rn(X0.x, X0.y);
        __half2 p1 = __floats2half2_rn(X0.z, X0.w);
        __half2 p2 = __floats2half2_rn(X1.x, X1.y);
        __half2 p3 = __floats2half2_rn(X1.z, X1.w);
        uint4 st;
        st.x = *(uint32_t*)&p0; st.y = *(uint32_t*)&p1;
        st.z = *(uint32_t*)&p2; st.w = *(uint32_t*)&p3;
        ((uint4*)(g_xh + (size_t)v * DIM))[lane] = st;
    }

    ((float4*)sacc[wid])[2 * lane]     = make_float4(acc[0], acc[1], acc[2], acc[3]);
    ((float4*)sacc[wid])[2 * lane + 1] = make_float4(acc[4], acc[5], acc[6], acc[7]);
    __syncthreads();

    float inv = 1.f / ((float)(ve - vs) + 1e-8f);
    int t = threadIdx.x;
    float2 p0 = ((const float2*)sacc[0])[t], p1 = ((const float2*)sacc[1])[t];
    float2 p2 = ((const float2*)sacc[2])[t], p3 = ((const float2*)sacc[3])[t];
    float r0 = (p0.x + p1.x + p2.x + p3.x) * inv;
    float r1 = (p0.y + p1.y + p2.y + p3.y) * inv;
    ((__half2*)buf)[(size_t)g * 256 + t] = __floats2half2_rn(r0, r1);
}

// --------------------- fused attention + readout (fp16 x) ------------------
// One block (128 thr, 4 warps) per graph; warps split nodes stride-4;
// online softmax per warp (m0 = 0), merged in smem. Lane owns dims 8l..8l+7.
// h read as fp16 from the h-half of buf (written by previous GEMM epilogue).
__global__ void __launch_bounds__(128)
attn_kernel(__half* __restrict__ buf, float* __restrict__ out, int G, int last) {
    int g = blockIdx.x;
    int lane = threadIdx.x & 31, wid = threadIdx.x >> 5;
    int vs = g_offs[g], ve = g_offs[g + 1];

    __shared__ float sm[4], sd[4];
    __shared__ float sacc[4][256];

    uint4 hraw = ((const uint4*)(buf + (size_t)g * KCAT + DIM))[lane];
    float h[8];
    unpack8(hraw, h);
    float acc[8];
#pragma unroll
    for (int j = 0; j < 8; ++j) acc[j] = 0.f;
    float m = 0.f, dd = 0.f;

    const uint4* xb = (const uint4*)g_xh;
    int v = vs + wid;
    for (; v + 4 < ve; v += 8) {
        uint4 rA = __ldcs(xb + (size_t)v * 32 + lane);    // evict-first
        uint4 rB = __ldcs(xb + (size_t)(v + 4) * 32 + lane);
        float XA[8], XB[8];
        unpack8(rA, XA); unpack8(rB, XB);
        float pA = XA[0] * h[0], pB = XB[0] * h[0];
#pragma unroll
        for (int j = 1; j < 8; ++j) {
            pA = fmaf(XA[j], h[j], pA);
            pB = fmaf(XB[j], h[j], pB);
        }
#pragma unroll
        for (int o = 16; o; o >>= 1) {
            pA += __shfl_xor_sync(0xffffffffu, pA, o);
            pB += __shfl_xor_sync(0xffffffffu, pB, o);
        }
        float mn = fmaxf(m, fmaxf(pA, pB));
        float sc = __expf(m - mn), eA = __expf(pA - mn), eB = __expf(pB - mn);
        dd = dd * sc + eA + eB;
#pragma unroll
        for (int j = 0; j < 8; ++j)
            acc[j] = fmaf(acc[j], sc, fmaf(XA[j], eA, XB[j] * eB));
        m = mn;
    }
    if (v < ve) {
        uint4 rA = __ldcs(xb + (size_t)v * 32 + lane);
        float XA[8];
        unpack8(rA, XA);
        float p = XA[0] * h[0];
#pragma unroll
        for (int j = 1; j < 8; ++j) p = fmaf(XA[j], h[j], p);
#pragma unroll
        for (int o = 16; o; o >>= 1) p += __shfl_xor_sync(0xffffffffu, p, o);
        float mn = fmaxf(m, p);
        float sc = __expf(m - mn), e = __expf(p - mn);
        dd = dd * sc + e;
#pragma unroll
        for (int j = 0; j < 8; ++j) acc[j] = fmaf(acc[j], sc, XA[j] * e);
        m = mn;
    }

    if (lane == 0) { sm[wid] = m; sd[wid] = dd; }
    ((float4*)sacc[wid])[2 * lane]     = make_float4(acc[0], acc[1], acc[2], acc[3]);
    ((float4*)sacc[wid])[2 * lane + 1] = make_float4(acc[4], acc[5], acc[6], acc[7]);
    __syncthreads();

    float M = fmaxf(fmaxf(sm[0], sm[1]), fmaxf(sm[2], sm[3]));
    float e0 = __expf(sm[0] - M), e1 = __expf(sm[1] - M);
    float e2 = __expf(sm[2] - M), e3 = __expf(sm[3] - M);
    float D = sd[0] * e0 + sd[1] * e1 + sd[2] * e2 + sd[3] * e3;
    float inv = 1.f / (D + 1e-8f);

    int t = threadIdx.x;
    float2 p0 = ((const float2*)sacc[0])[t], p1 = ((const float2*)sacc[1])[t];
    float2 p2 = ((const float2*)sacc[2])[t], p3 = ((const float2*)sacc[3])[t];
    float r0 = (p0.x * e0 + p1.x * e1 + p2.x * e2 + p3.x * e3) * inv;
    float r1 = (p0.y * e0 + p1.y * e1 + p2.y * e2 + p3.y * e3) * inv;
    ((__half2*)buf)[(size_t)g * 256 + t] = __floats2half2_rn(r0, r1);
    if (last) {
        float2* o2 = (float2*)(out + (size_t)g * 512 + DIM);
        o2[t] = make_float2(r0, r1);
    }
}

// ------------------- fp16 mma.sync GEMM + fused LSTM (R14) -----------------
// CTA tile 128(M)x64(N), 8 warps (4x2), warp tile 32x32, BK=64.
// 2 stages x 24KB smem, regs<=64 -> 4 CTAs/SM.
// Single __syncthreads per chunk: wait(0) -> sync -> load(c+1) -> compute(c).
#define NSTAGE 2
#define A_TILE 16384                   // 128 rows x 128B
#define B_TILE 8192                    // 64 rows x 128B
#define STAGE_BYTES (A_TILE + B_TILE)  // 24576
#define GEMM_SMEM (NSTAGE * STAGE_BYTES)
#define GS_STRIDE 66                   // staging row stride in floats (8B-aligned)

__global__ void __launch_bounds__(256, 4)
gemm_lstm_kernel(const __half* __restrict__ A, __half* __restrict__ Anext,
                 float* __restrict__ out, int M, int last, int nchunk) {
    extern __shared__ __align__(128) char smem[];
    uint32_t sbase = smem_u32(smem);
    const int tid = threadIdx.x;
    const int wid = tid >> 5, lane = tid & 31;
    const int wm = wid & 3, wn = wid >> 2;       // 4(M) x 2(N) warp grid
    const int bn = blockIdx.x, bm = blockIdx.y;

    auto load_chunk = [&](int c, int s) {
#pragma unroll
        for (int i = 0; i < 6; ++i) {
            int q = i * 256 + tid;                // 0..1535
            uint32_t dst;
            const __half* src;
            if (q < 1024) {                       // A: 128 rows x 8 c4
                int row = q >> 3, c4 = q & 7;
                dst = sbase + s * STAGE_BYTES + (uint32_t)row * 128
                    + (uint32_t)((c4 ^ (row & 7)) << 4);
                int rA = bm * 128 + row; if (rA >= M) rA = M - 1;
                src = A + (size_t)rA * KCAT + c * 64 + c4 * 8;
            } else {                              // B: 64 rows x 8 c4
                int qb = q - 1024;
                int row = qb >> 3, c4 = qb & 7;
                dst = sbase + s * STAGE_BYTES + A_TILE + (uint32_t)row * 128
                    + (uint32_t)((c4 ^ (row & 7)) << 4);
                src = g_Wcat + (size_t)(bn * 64 + row) * KCAT + c * 64 + c4 * 8;
            }
            CP_ASYNC16(dst, src);
        }
        CP_COMMIT();
    };

    load_chunk(0, 0);    // prologue

    float acc[2][4][4];
#pragma unroll
    for (int mt = 0; mt < 2; ++mt)
#pragma unroll
        for (int nt = 0; nt < 4; ++nt)
#pragma unroll
            for (int r = 0; r < 4; ++r) acc[mt][nt][r] = 0.f;

    const int mgrp = lane >> 3, mrow = lane & 7;
    const int arow_off = ((mgrp & 1) << 3) + mrow;
    const int akb_off = mgrp >> 1;
    const int brow_off = ((mgrp >> 1) << 3) + mrow;
    const int bkb_off = mgrp & 1;

    uint32_t aRowBase[2], aSwz[2];
#pragma unroll
    for (int mt = 0; mt < 2; ++mt) {
        int row = wm * 32 + mt * 16 + arow_off;
        aRowBase[mt] = (uint32_t)row * 128;
        aSwz[mt] = (uint32_t)(row & 7);
    }
    uint32_t bRowBase[2], bSwz[2];
#pragma unroll
    for (int p = 0; p < 2; ++p) {
        int n = wn * 32 + p * 16 + brow_off;
        bRowBase[p] = (uint32_t)n * 128;
        bSwz[p] = (uint32_t)(n & 7);
    }

    // single-sync double-buffered mainloop
    for (int c = 0; c < nchunk; ++c) {
        const int s = c & 1;
        asm volatile("cp.async.wait_group 0;" ::: "memory");   // chunk c landed
        __syncthreads();   // publish chunk c; all warps done computing c-1
        if (c + 1 < nchunk) load_chunk(c + 1, (c + 1) & 1);    // stage free (WAR ok)
        uint32_t aS = sbase + (uint32_t)s * STAGE_BYTES;
        uint32_t bS = aS + A_TILE;
#pragma unroll
        for (int kk = 0; kk < 4; ++kk) {
            uint32_t af[2][4], bf[4][2];
#pragma unroll
            for (int mt = 0; mt < 2; ++mt) {
                uint32_t kb = (uint32_t)(kk * 2 + akb_off) ^ aSwz[mt];
                LDMATRIX_X4(af[mt][0], af[mt][1], af[mt][2], af[mt][3],
                            aS + aRowBase[mt] + (kb << 4));
            }
#pragma unroll
            for (int p = 0; p < 2; ++p) {
                uint32_t kb = (uint32_t)(kk * 2 + bkb_off) ^ bSwz[p];
                LDMATRIX_X4(bf[2 * p][0], bf[2 * p][1], bf[2 * p + 1][0], bf[2 * p + 1][1],
                            bS + bRowBase[p] + (kb << 4));
            }
#pragma unroll
            for (int mt = 0; mt < 2; ++mt)
#pragma unroll
                for (int nt = 0; nt < 4; ++nt)
                    mma_f16(acc[mt][nt], af[mt], bf[nt]);
        }
    }
    __syncthreads();   // last chunk's smem reads done before staging reuses smem

    // ---- epilogue phase 1: stage raw gate fragments to smem ----
    float* gs = (float*)smem;              // [128][GS_STRIDE]
    {
        const int grow = wm * 32 + (lane >> 2);
        const int gcol = wn * 32 + (lane & 3) * 2;
#pragma unroll
        for (int mt = 0; mt < 2; ++mt)
#pragma unroll
            for (int nt = 0; nt < 4; ++nt) {
                int r0 = grow + mt * 16;
                int cc = gcol + nt * 8;
                *(float2*)&gs[r0 * GS_STRIDE + cc] =
                    make_float2(acc[mt][nt][0], acc[mt][nt][1]);
                *(float2*)&gs[(r0 + 8) * GS_STRIDE + cc] =
                    make_float2(acc[mt][nt][2], acc[mt][nt][3]);
            }
    }
    __syncthreads();

    // ---- epilogue phase 2: coalesced LSTM (thread = half g-row, 8 d) ----
    {
        int gl = tid >> 1, half = tid & 1;
        int g = bm * 128 + gl;
        if (g < M) {
            const float* row = gs + gl * GS_STRIDE + half * 32;   // 8B-aligned
            const float4* bs = (const float4*)(g_bsum + bn * 64 + half * 32);
            int dg = bn * 16 + half * 8;
            float* crow = g_c + (size_t)g * DIM + dg;
            float cv[8], hv[8];
#pragma unroll
            for (int i = 0; i < 8; ++i) {
                float2 v01 = *(const float2*)(row + i * 4);
                float2 v23 = *(const float2*)(row + i * 4 + 2);
                float4 b = __ldg(bs + i);
                float gi = sigm(v01.x + b.x);
                float gf = sigm(v01.y + b.y);
                float gg = ftanh(v23.x + b.z);
                float go = sigm(v23.y + b.w);
                float cn = gf * crow[i] + gi * gg;
                cv[i] = cn;
                hv[i] = go * ftanh(cn);
            }
            if (last) {
                float4* o = (float4*)(out + (size_t)g * 512 + dg);
                o[0] = make_float4(hv[0], hv[1], hv[2], hv[3]);
                o[1] = make_float4(hv[4], hv[5], hv[6], hv[7]);
            } else {
                float4* cw = (float4*)crow;
                cw[0] = make_float4(cv[0], cv[1], cv[2], cv[3]);
                cw[1] = make_float4(cv[4], cv[5], cv[6], cv[7]);
                __half2 hh[4];
#pragma unroll
                for (int i = 0; i < 4; ++i)
                    hh[i] = __floats2half2_rn(hv[2 * i], hv[2 * i + 1]);
                *(uint4*)(Anext + (size_t)g * KCAT + DIM + dg) = *(uint4*)hh;
            }
        }
    }
}

// ------------------------------ launch -------------------------------------
extern "C" void kernel_launch(void* const* d_in, const int* in_sizes, int n_in,
                              void* d_out, int out_size) {
    const float* x     = (const float*)d_in[0];
    const int*   batch = (const int*)d_in[1];
    const float* W_ih  = (const float*)d_in[3];
    const float* W_hh  = (const float*)d_in[4];
    const float* b_ih  = (const float*)d_in[5];
    const float* b_hh  = (const float*)d_in[6];
    float* out = (float*)d_out;

    int N = in_sizes[1];
    int G = out_size / (2 * DIM);

    __half *A0, *A1;
    cudaGetSymbolAddress((void**)&A0, g_A0);
    cudaGetSymbolAddress((void**)&A1, g_A1);

    cudaFuncSetAttribute(gemm_lstm_kernel,
                         cudaFuncAttributeMaxDynamicSharedMemorySize, GEMM_SMEM);

    // launch order: index 3 = gemm0 (ncu profile slot)
    setup_kernel<<<(G * DIM + 255) / 256, 256>>>(W_ih, W_hh, b_ih, b_hh, G); // 0
    offsets_kernel<<<(N + 255) / 256, 256>>>(batch, N, G);                   // 1
    convert_mean_kernel<<<G, 128>>>(x, A0, G);                               // 2

    dim3 gemm_grid(GDIM4 / 64, (G + 127) / 128);
    for (int it = 0; it < 6; ++it) {
        __half* cur = (it & 1) ? A1 : A0;
        __half* nxt = (it & 1) ? A0 : A1;
        int last = (it == 5) ? 1 : 0;
        int nchunk = (it == 0) ? 4 : 8;   // iter0: h==0, K=256 exact
        if (it > 0) attn_kernel<<<G, 128>>>(cur, out, G, last);
        gemm_lstm_kernel<<<gemm_grid, 256, GEMM_SMEM>>>(cur, nxt, out, G, last, nchunk);
    }
}